// round 1
// baseline (speedup 1.0000x reference)
#include <cuda_runtime.h>
#include <math.h>

#define TOTE (4096 * 768)

// Scratch (allocation-free rule: __device__ globals)
__device__ float g_qkv[3 * TOTE];   // [q|k|v], each [4096, 768]
__device__ float g_att[TOTE];       // attention output before final projection

// ---------------------------------------------------------------------------
// NT SGEMM: C[m,n] = sum_k A[m,k] * B[n,k]  (+ optional bias[n])
// M = 4096, N = 768, K = 768 fixed. Tile 128x128x16, 256 threads, 8x8/thread.
// blockIdx.z selects among three weight matrices (QKV fused launch).
// ---------------------------------------------------------------------------
__global__ __launch_bounds__(256) void sgemm_nt(
    const float* __restrict__ A,
    const float* __restrict__ B0, const float* __restrict__ B1,
    const float* __restrict__ B2,
    const float* __restrict__ bias, float* __restrict__ C)
{
    const int LD = 768;
    const float* B = (blockIdx.z == 0) ? B0 : ((blockIdx.z == 1) ? B1 : B2);
    float* Cz = C + (size_t)blockIdx.z * TOTE;
    const int m0 = blockIdx.y * 128;
    const int n0 = blockIdx.x * 128;

    __shared__ float As[16][128];
    __shared__ float Bs[16][128];

    const int tid = threadIdx.x;
    const int tx = tid & 15, ty = tid >> 4;
    const int lr = tid >> 2;           // 0..63
    const int lc = (tid & 3) << 2;     // 0,4,8,12

    float acc[8][8];
#pragma unroll
    for (int i = 0; i < 8; i++)
#pragma unroll
        for (int j = 0; j < 8; j++) acc[i][j] = 0.f;

    for (int k0 = 0; k0 < 768; k0 += 16) {
#pragma unroll
        for (int hh = 0; hh < 2; hh++) {
            int row = lr + hh * 64;
            float4 a = *(const float4*)(A + (size_t)(m0 + row) * LD + k0 + lc);
            As[lc + 0][row] = a.x; As[lc + 1][row] = a.y;
            As[lc + 2][row] = a.z; As[lc + 3][row] = a.w;
            float4 bq = *(const float4*)(B + (size_t)(n0 + row) * LD + k0 + lc);
            Bs[lc + 0][row] = bq.x; Bs[lc + 1][row] = bq.y;
            Bs[lc + 2][row] = bq.z; Bs[lc + 3][row] = bq.w;
        }
        __syncthreads();
#pragma unroll
        for (int kk = 0; kk < 16; kk++) {
            float ra[8], rb[8];
            *(float4*)&ra[0] = *(const float4*)&As[kk][ty * 8];
            *(float4*)&ra[4] = *(const float4*)&As[kk][ty * 8 + 4];
            *(float4*)&rb[0] = *(const float4*)&Bs[kk][tx * 8];
            *(float4*)&rb[4] = *(const float4*)&Bs[kk][tx * 8 + 4];
#pragma unroll
            for (int i = 0; i < 8; i++)
#pragma unroll
                for (int j = 0; j < 8; j++)
                    acc[i][j] = fmaf(ra[i], rb[j], acc[i][j]);
        }
        __syncthreads();
    }

#pragma unroll
    for (int i = 0; i < 8; i++) {
        int m = m0 + ty * 8 + i;
#pragma unroll
        for (int j = 0; j < 8; j += 4) {
            int n = n0 + tx * 8 + j;
            float4 v = make_float4(acc[i][j], acc[i][j + 1], acc[i][j + 2], acc[i][j + 3]);
            if (bias) {
                float4 bb = *(const float4*)(bias + n);
                v.x += bb.x; v.y += bb.y; v.z += bb.z; v.w += bb.w;
            }
            *(float4*)(Cz + (size_t)m * LD + n) = v;
        }
    }
}

// ---------------------------------------------------------------------------
// Fused biased flash attention (fp32).
// Key identity: softmax(W + log_softmax(scale*QK^T)) == softmax(W + scale*QK^T)
// since log_softmax subtracts a per-row constant (LSE) that softmax ignores.
//
// Grid: (16 n-tiles, 12 heads, 4 batch). Block: 256 threads.
// Per block: 64 query rows; stream S=1024 in 64-wide tiles with online softmax.
// Thread (tx,ty) owns a 4x4 register tile for both score and output GEMMs.
// attn_weight (192 MB) is streamed exactly once straight into the score regs.
// ---------------------------------------------------------------------------
__global__ __launch_bounds__(256) void attn_fused(
    const float* __restrict__ qkv, const float* __restrict__ W,
    float* __restrict__ out)
{
    const int n0 = blockIdx.x * 64;
    const int h  = blockIdx.y;
    const int b  = blockIdx.z;

    extern __shared__ float sm[];
    float (*q_s)[68] = (float(*)[68])(sm);             // [d][q]  transposed
    float (*k_s)[68] = (float(*)[68])(sm + 64 * 68);   // [d][s]  transposed
    float (*v_s)[68] = (float(*)[68])(sm + 2 * 64 * 68); // [s][d] natural
    float (*p_s)[68] = (float(*)[68])(sm + 3 * 64 * 68); // [s][q] transposed

    const float* qg = qkv + ((size_t)b * 1024 + n0) * 768 + h * 64;
    const float* kg = qkv + (size_t)TOTE + (size_t)b * 1024 * 768 + h * 64;
    const float* vg = kg + (size_t)TOTE;
    const float* wg = W + ((size_t)(b * 12 + h) * 1024 + n0) * 1024;

    const int tid = threadIdx.x;
    const int tx = tid & 15, ty = tid >> 4;

    // Load Q tile [64 rows x 64 d] transposed into q_s[d][q]
#pragma unroll
    for (int e = 0; e < 4; e++) {
        int idx = e * 256 + tid;
        int r = idx >> 4, fg = (idx & 15) << 2;
        float4 v = *(const float4*)(qg + (size_t)r * 768 + fg);
        q_s[fg + 0][r] = v.x; q_s[fg + 1][r] = v.y;
        q_s[fg + 2][r] = v.z; q_s[fg + 3][r] = v.w;
    }

    float acc[4][4];
    float mrow[4], lrow[4];
#pragma unroll
    for (int i = 0; i < 4; i++) {
        mrow[i] = -INFINITY; lrow[i] = 0.f;
#pragma unroll
        for (int j = 0; j < 4; j++) acc[i][j] = 0.f;
    }
    const float scale = 0.125f;  // 1/sqrt(64)

    for (int s0 = 0; s0 < 1024; s0 += 64) {
        __syncthreads();  // prior PV reads of k_s/v_s/p_s done (also covers q on iter 0)
        // Load K tile transposed, V tile natural
#pragma unroll
        for (int e = 0; e < 4; e++) {
            int idx = e * 256 + tid;
            int r = idx >> 4, fg = (idx & 15) << 2;
            float4 kv = *(const float4*)(kg + (size_t)(s0 + r) * 768 + fg);
            k_s[fg + 0][r] = kv.x; k_s[fg + 1][r] = kv.y;
            k_s[fg + 2][r] = kv.z; k_s[fg + 3][r] = kv.w;
            float4 vv = *(const float4*)(vg + (size_t)(s0 + r) * 768 + fg);
            *(float4*)&v_s[r][fg] = vv;
        }
        __syncthreads();

        // Scores: 4x4 per thread over d=64
        float sc[4][4];
#pragma unroll
        for (int i = 0; i < 4; i++)
#pragma unroll
            for (int j = 0; j < 4; j++) sc[i][j] = 0.f;
#pragma unroll
        for (int d = 0; d < 64; d++) {
            float4 qv = *(const float4*)&q_s[d][ty * 4];
            float4 kv = *(const float4*)&k_s[d][tx * 4];
            float rq[4] = {qv.x, qv.y, qv.z, qv.w};
            float rk[4] = {kv.x, kv.y, kv.z, kv.w};
#pragma unroll
            for (int i = 0; i < 4; i++)
#pragma unroll
                for (int j = 0; j < 4; j++)
                    sc[i][j] = fmaf(rq[i], rk[j], sc[i][j]);
        }

        // Fuse bias: s = scale*qk + attn_weight (streamed once from HBM)
#pragma unroll
        for (int i = 0; i < 4; i++) {
            float4 w4 = *(const float4*)(wg + (size_t)(ty * 4 + i) * 1024 + s0 + tx * 4);
            sc[i][0] = fmaf(sc[i][0], scale, w4.x);
            sc[i][1] = fmaf(sc[i][1], scale, w4.y);
            sc[i][2] = fmaf(sc[i][2], scale, w4.z);
            sc[i][3] = fmaf(sc[i][3], scale, w4.w);
        }

        // Online softmax. Row-reduce across the 16 tx lanes (xor <= 8 stays
        // inside each 16-lane half of the warp).
#pragma unroll
        for (int i = 0; i < 4; i++) {
            float mx = fmaxf(fmaxf(sc[i][0], sc[i][1]), fmaxf(sc[i][2], sc[i][3]));
#pragma unroll
            for (int o = 1; o < 16; o <<= 1)
                mx = fmaxf(mx, __shfl_xor_sync(0xffffffffu, mx, o));
            float mnew = fmaxf(mrow[i], mx);
            float corr = __expf(mrow[i] - mnew);
            mrow[i] = mnew;
            float rs = 0.f;
#pragma unroll
            for (int j = 0; j < 4; j++) {
                float p = __expf(sc[i][j] - mnew);
                sc[i][j] = p;
                rs += p;
            }
#pragma unroll
            for (int o = 1; o < 16; o <<= 1)
                rs += __shfl_xor_sync(0xffffffffu, rs, o);
            lrow[i] = lrow[i] * corr + rs;
#pragma unroll
            for (int j = 0; j < 4; j++) acc[i][j] *= corr;
        }

        // Stage P transposed for the PV GEMM
#pragma unroll
        for (int i = 0; i < 4; i++)
#pragma unroll
            for (int j = 0; j < 4; j++)
                p_s[tx * 4 + j][ty * 4 + i] = sc[i][j];
        __syncthreads();

        // acc += P @ V  (4x4 per thread over s=64)
#pragma unroll
        for (int s = 0; s < 64; s++) {
            float4 pv = *(const float4*)&p_s[s][ty * 4];
            float4 vv = *(const float4*)&v_s[s][tx * 4];
            float rp[4] = {pv.x, pv.y, pv.z, pv.w};
            float rv[4] = {vv.x, vv.y, vv.z, vv.w};
#pragma unroll
            for (int i = 0; i < 4; i++)
#pragma unroll
                for (int j = 0; j < 4; j++)
                    acc[i][j] = fmaf(rp[i], rv[j], acc[i][j]);
        }
    }

    // Normalize and write [64 x 64] output tile
    float* og = out + ((size_t)b * 1024 + n0) * 768 + h * 64;
#pragma unroll
    for (int i = 0; i < 4; i++) {
        float inv = 1.f / lrow[i];
        float4 v = make_float4(acc[i][0] * inv, acc[i][1] * inv,
                               acc[i][2] * inv, acc[i][3] * inv);
        *(float4*)(og + (size_t)(ty * 4 + i) * 768 + tx * 4) = v;
    }
}

// ---------------------------------------------------------------------------
// Launch
// ---------------------------------------------------------------------------
extern "C" void kernel_launch(void* const* d_in, const int* in_sizes, int n_in,
                              void* d_out, int out_size)
{
    const float* query = (const float*)d_in[0];
    const float* attw  = (const float*)d_in[1];
    const float* Wq    = (const float*)d_in[2];
    const float* Wk    = (const float*)d_in[3];
    const float* Wv    = (const float*)d_in[4];
    const float* Wo    = (const float*)d_in[5];
    const float* bo    = (const float*)d_in[6];
    float* out = (float*)d_out;

    float* qkv = nullptr;
    float* att = nullptr;
    cudaGetSymbolAddress((void**)&qkv, g_qkv);
    cudaGetSymbolAddress((void**)&att, g_att);

    const int smem = 4 * 64 * 68 * (int)sizeof(float);  // 69632 B
    cudaFuncSetAttribute(attn_fused, cudaFuncAttributeMaxDynamicSharedMemorySize, smem);

    // 1) Q,K,V projections (one launch, z selects weight)
    sgemm_nt<<<dim3(6, 32, 3), 256>>>(query, Wq, Wk, Wv, nullptr, qkv);
    // 2) Fused biased attention
    attn_fused<<<dim3(16, 12, 4), 256, smem>>>(qkv, attw, att);
    // 3) Output projection + bias
    sgemm_nt<<<dim3(6, 32, 1), 256>>>(att, Wo, Wo, Wo, bo, out);
}

// round 4
// speedup vs baseline: 1.4438x; 1.4438x over previous
#include <cuda_runtime.h>
#include <cuda_bf16.h>
#include <math.h>
#include <cstdint>

#define TOTE (4096 * 768)
#define WELE (768 * 768)

// Scratch (allocation-free rule: __device__ globals)
__device__ float g_qkv[3 * TOTE];                 // q|k|v fp32, each [4096,768]
__device__ float g_att[TOTE];                     // attention out pre-projection
__device__ __nv_bfloat16 g_ahi[TOTE];             // activation split (query, then att)
__device__ __nv_bfloat16 g_alo[TOTE];
__device__ __nv_bfloat16 g_whi[4 * WELE];         // Wq|Wk|Wv|Wo split
__device__ __nv_bfloat16 g_wlo[4 * WELE];

// ===========================================================================
// Helpers: base-sm_103-safe warp MMA (no tcgen05 — ptxas target is compute_103,
// which rejects arch-conditional 'a' features; HMMA/ldmatrix are sm_80-era).
// ===========================================================================
__device__ __forceinline__ uint32_t smem_u32(const void* p) {
    uint32_t a;
    asm("{ .reg .u64 t; cvta.to.shared.u64 t, %1; cvt.u32.u64 %0, t; }" : "=r"(a) : "l"(p));
    return a;
}
__device__ __forceinline__ void ldsm_x4(uint32_t* r, uint32_t addr) {
    asm volatile("ldmatrix.sync.aligned.m8n8.x4.shared.b16 {%0,%1,%2,%3}, [%4];"
                 : "=r"(r[0]), "=r"(r[1]), "=r"(r[2]), "=r"(r[3]) : "r"(addr));
}
__device__ __forceinline__ void mma16816(float* d, const uint32_t* a,
                                         uint32_t b0, uint32_t b1) {
    asm volatile(
        "mma.sync.aligned.m16n8k16.row.col.f32.bf16.bf16.f32 "
        "{%0,%1,%2,%3}, {%4,%5,%6,%7}, {%8,%9}, {%0,%1,%2,%3};"
        : "+f"(d[0]), "+f"(d[1]), "+f"(d[2]), "+f"(d[3])
        : "r"(a[0]), "r"(a[1]), "r"(a[2]), "r"(a[3]), "r"(b0), "r"(b1));
}

// ===========================================================================
// fp32 -> bf16 hi/lo split (Ozaki 2-term decomposition)
// ===========================================================================
__global__ __launch_bounds__(256) void split_f32(
    const float4* __restrict__ x, uint2* __restrict__ hi, uint2* __restrict__ lo, int n4)
{
    int i = blockIdx.x * blockDim.x + threadIdx.x;
    if (i >= n4) return;
    float4 v = x[i];
    float vv[4] = {v.x, v.y, v.z, v.w};
    __nv_bfloat16 h[4], l[4];
#pragma unroll
    for (int j = 0; j < 4; j++) {
        h[j] = __float2bfloat16(vv[j]);
        l[j] = __float2bfloat16(vv[j] - __bfloat162float(h[j]));
    }
    hi[i] = *(uint2*)h;
    lo[i] = *(uint2*)l;
}

// ===========================================================================
// HMMA split-bf16 NT GEMM: C[m,n] = sum_k A[m,k]*B[n,k] (+bias)
// Block 128x128 tile, 8 warps (4m x 2n), warp tile 32x64.
// K in chunks of 64; 3 terms (hi*hi, lo*hi, hi*lo) share fp32 accumulators.
// Smem row stride 72 bf16 (144 B): 8 ldmatrix rows cover all 32 banks once.
// blockIdx.z selects weight slot + output slab (QKV fused in one launch).
// ===========================================================================
#define AST 72

__global__ __launch_bounds__(256) void gemm_mma(
    const __nv_bfloat16* __restrict__ Ahi, const __nv_bfloat16* __restrict__ Alo,
    const __nv_bfloat16* __restrict__ Whi, const __nv_bfloat16* __restrict__ Wlo,
    const float* __restrict__ bias, float* __restrict__ C)
{
    extern __shared__ __align__(16) __nv_bfloat16 smb[];
    __nv_bfloat16* sAh = smb;
    __nv_bfloat16* sAl = sAh + 128 * AST;
    __nv_bfloat16* sBh = sAl + 128 * AST;
    __nv_bfloat16* sBl = sBh + 128 * AST;

    const int tid = threadIdx.x, wid = tid >> 5, lane = tid & 31;
    const int wm = (wid >> 1) * 32;   // warp m offset (0,32,64,96)
    const int wn = (wid & 1) * 64;    // warp n offset (0,64)
    const int m0 = blockIdx.y * 128, n0 = blockIdx.x * 128;

    const __nv_bfloat16* gAh = Ahi + (size_t)m0 * 768;
    const __nv_bfloat16* gAl = Alo + (size_t)m0 * 768;
    const __nv_bfloat16* gBh = Whi + (size_t)blockIdx.z * WELE + (size_t)n0 * 768;
    const __nv_bfloat16* gBl = Wlo + (size_t)blockIdx.z * WELE + (size_t)n0 * 768;
    float* Cz = C + (size_t)blockIdx.z * TOTE;

    float acc[2][8][4];
#pragma unroll
    for (int i = 0; i < 2; i++)
#pragma unroll
        for (int j = 0; j < 8; j++)
#pragma unroll
            for (int k = 0; k < 4; k++) acc[i][j][k] = 0.f;

    // Per-lane ldmatrix base addresses (row = lane&15, col-half = lane>>4)
    const int lrow = lane & 15;
    const int lcol8 = (lane >> 4) * 8;
    const uint32_t aAh = smem_u32(sAh + (wm + lrow) * AST + lcol8);
    const uint32_t aAl = smem_u32(sAl + (wm + lrow) * AST + lcol8);
    const uint32_t aBh = smem_u32(sBh + (wn + lrow) * AST + lcol8);
    const uint32_t aBl = smem_u32(sBl + (wn + lrow) * AST + lcol8);

    for (int k0 = 0; k0 < 768; k0 += 64) {
        __syncthreads();
        // Stage 4 tiles of [128 x 64] bf16, uint2 (4 bf16) per transfer
#pragma unroll
        for (int it = 0; it < 8; it++) {
            int idx = it * 256 + tid;
            int row = idx >> 4, c4 = (idx & 15) << 2;
            *(uint2*)(sAh + row * AST + c4) = *(const uint2*)(gAh + (size_t)row * 768 + k0 + c4);
            *(uint2*)(sAl + row * AST + c4) = *(const uint2*)(gAl + (size_t)row * 768 + k0 + c4);
            *(uint2*)(sBh + row * AST + c4) = *(const uint2*)(gBh + (size_t)row * 768 + k0 + c4);
            *(uint2*)(sBl + row * AST + c4) = *(const uint2*)(gBl + (size_t)row * 768 + k0 + c4);
        }
        __syncthreads();

#pragma unroll
        for (int kk = 0; kk < 64; kk += 16) {
            const uint32_t koff = kk * 2;  // bytes
            uint32_t ah[2][4], al[2][4], bh[4][4], bl[4][4];
#pragma unroll
            for (int mf = 0; mf < 2; mf++) {
                ldsm_x4(ah[mf], aAh + mf * 16 * AST * 2 + koff);
                ldsm_x4(al[mf], aAl + mf * 16 * AST * 2 + koff);
            }
#pragma unroll
            for (int nq = 0; nq < 4; nq++) {
                ldsm_x4(bh[nq], aBh + nq * 16 * AST * 2 + koff);
                ldsm_x4(bl[nq], aBl + nq * 16 * AST * 2 + koff);
            }
            // x4 on B yields: nfrag(2*nq)   b = {r0, r2}
            //                 nfrag(2*nq+1) b = {r1, r3}
#pragma unroll
            for (int mf = 0; mf < 2; mf++) {
#pragma unroll
                for (int nq = 0; nq < 4; nq++) {
                    float* a0 = acc[mf][nq * 2 + 0];
                    float* a1 = acc[mf][nq * 2 + 1];
                    mma16816(a0, ah[mf], bh[nq][0], bh[nq][2]);   // hi*hi
                    mma16816(a1, ah[mf], bh[nq][1], bh[nq][3]);
                    mma16816(a0, al[mf], bh[nq][0], bh[nq][2]);   // lo*hi
                    mma16816(a1, al[mf], bh[nq][1], bh[nq][3]);
                    mma16816(a0, ah[mf], bl[nq][0], bl[nq][2]);   // hi*lo
                    mma16816(a1, ah[mf], bl[nq][1], bl[nq][3]);
                }
            }
        }
    }

    // Epilogue: acc frag (mf,nf): rows wm+mf*16+(lane>>2)+{0,8}, cols wn+nf*8+(lane&3)*2
#pragma unroll
    for (int mf = 0; mf < 2; mf++) {
#pragma unroll
        for (int nf = 0; nf < 8; nf++) {
            int row = m0 + wm + mf * 16 + (lane >> 2);
            int col = n0 + wn + nf * 8 + (lane & 3) * 2;
            float2 v0 = make_float2(acc[mf][nf][0], acc[mf][nf][1]);
            float2 v1 = make_float2(acc[mf][nf][2], acc[mf][nf][3]);
            if (bias) {
                float b0 = bias[col], b1 = bias[col + 1];
                v0.x += b0; v0.y += b1; v1.x += b0; v1.y += b1;
            }
            *(float2*)(Cz + (size_t)row * 768 + col) = v0;
            *(float2*)(Cz + (size_t)(row + 8) * 768 + col) = v1;
        }
    }
}

// ===========================================================================
// Fused biased flash attention (fp32) — unchanged (correct since Round 1).
// softmax(W + log_softmax(s*QK^T)) == softmax(W + s*QK^T)  (LSE cancels)
// ===========================================================================
__global__ __launch_bounds__(256) void attn_fused(
    const float* __restrict__ qkv, const float* __restrict__ W,
    float* __restrict__ out)
{
    const int n0 = blockIdx.x * 64;
    const int h  = blockIdx.y;
    const int b  = blockIdx.z;

    extern __shared__ float sm[];
    float (*q_s)[68] = (float(*)[68])(sm);
    float (*k_s)[68] = (float(*)[68])(sm + 64 * 68);
    float (*v_s)[68] = (float(*)[68])(sm + 2 * 64 * 68);
    float (*p_s)[68] = (float(*)[68])(sm + 3 * 64 * 68);

    const float* qg = qkv + ((size_t)b * 1024 + n0) * 768 + h * 64;
    const float* kg = qkv + (size_t)TOTE + (size_t)b * 1024 * 768 + h * 64;
    const float* vg = kg + (size_t)TOTE;
    const float* wg = W + ((size_t)(b * 12 + h) * 1024 + n0) * 1024;

    const int tid = threadIdx.x;
    const int tx = tid & 15, ty = tid >> 4;

#pragma unroll
    for (int e = 0; e < 4; e++) {
        int idx = e * 256 + tid;
        int r = idx >> 4, fg = (idx & 15) << 2;
        float4 v = *(const float4*)(qg + (size_t)r * 768 + fg);
        q_s[fg + 0][r] = v.x; q_s[fg + 1][r] = v.y;
        q_s[fg + 2][r] = v.z; q_s[fg + 3][r] = v.w;
    }

    float acc[4][4];
    float mrow[4], lrow[4];
#pragma unroll
    for (int i = 0; i < 4; i++) {
        mrow[i] = -INFINITY; lrow[i] = 0.f;
#pragma unroll
        for (int j = 0; j < 4; j++) acc[i][j] = 0.f;
    }
    const float scale = 0.125f;

    for (int s0 = 0; s0 < 1024; s0 += 64) {
        __syncthreads();
#pragma unroll
        for (int e = 0; e < 4; e++) {
            int idx = e * 256 + tid;
            int r = idx >> 4, fg = (idx & 15) << 2;
            float4 kv = *(const float4*)(kg + (size_t)(s0 + r) * 768 + fg);
            k_s[fg + 0][r] = kv.x; k_s[fg + 1][r] = kv.y;
            k_s[fg + 2][r] = kv.z; k_s[fg + 3][r] = kv.w;
            float4 vv = *(const float4*)(vg + (size_t)(s0 + r) * 768 + fg);
            *(float4*)&v_s[r][fg] = vv;
        }
        __syncthreads();

        float sc[4][4];
#pragma unroll
        for (int i = 0; i < 4; i++)
#pragma unroll
            for (int j = 0; j < 4; j++) sc[i][j] = 0.f;
#pragma unroll
        for (int d = 0; d < 64; d++) {
            float4 qv = *(const float4*)&q_s[d][ty * 4];
            float4 kv = *(const float4*)&k_s[d][tx * 4];
            float rq[4] = {qv.x, qv.y, qv.z, qv.w};
            float rk[4] = {kv.x, kv.y, kv.z, kv.w};
#pragma unroll
            for (int i = 0; i < 4; i++)
#pragma unroll
                for (int j = 0; j < 4; j++)
                    sc[i][j] = fmaf(rq[i], rk[j], sc[i][j]);
        }

#pragma unroll
        for (int i = 0; i < 4; i++) {
            float4 w4 = *(const float4*)(wg + (size_t)(ty * 4 + i) * 1024 + s0 + tx * 4);
            sc[i][0] = fmaf(sc[i][0], scale, w4.x);
            sc[i][1] = fmaf(sc[i][1], scale, w4.y);
            sc[i][2] = fmaf(sc[i][2], scale, w4.z);
            sc[i][3] = fmaf(sc[i][3], scale, w4.w);
        }

#pragma unroll
        for (int i = 0; i < 4; i++) {
            float mx = fmaxf(fmaxf(sc[i][0], sc[i][1]), fmaxf(sc[i][2], sc[i][3]));
#pragma unroll
            for (int o = 1; o < 16; o <<= 1)
                mx = fmaxf(mx, __shfl_xor_sync(0xffffffffu, mx, o));
            float mnew = fmaxf(mrow[i], mx);
            float corr = __expf(mrow[i] - mnew);
            mrow[i] = mnew;
            float rs = 0.f;
#pragma unroll
            for (int j = 0; j < 4; j++) {
                float p = __expf(sc[i][j] - mnew);
                sc[i][j] = p;
                rs += p;
            }
#pragma unroll
            for (int o = 1; o < 16; o <<= 1)
                rs += __shfl_xor_sync(0xffffffffu, rs, o);
            lrow[i] = lrow[i] * corr + rs;
#pragma unroll
            for (int j = 0; j < 4; j++) acc[i][j] *= corr;
        }

#pragma unroll
        for (int i = 0; i < 4; i++)
#pragma unroll
            for (int j = 0; j < 4; j++)
                p_s[tx * 4 + j][ty * 4 + i] = sc[i][j];
        __syncthreads();

#pragma unroll
        for (int s = 0; s < 64; s++) {
            float4 pv = *(const float4*)&p_s[s][ty * 4];
            float4 vv = *(const float4*)&v_s[s][tx * 4];
            float rp[4] = {pv.x, pv.y, pv.z, pv.w};
            float rv[4] = {vv.x, vv.y, vv.z, vv.w};
#pragma unroll
            for (int i = 0; i < 4; i++)
#pragma unroll
                for (int j = 0; j < 4; j++)
                    acc[i][j] = fmaf(rp[i], rv[j], acc[i][j]);
        }
    }

    float* og = out + ((size_t)b * 1024 + n0) * 768 + h * 64;
#pragma unroll
    for (int i = 0; i < 4; i++) {
        float inv = 1.f / lrow[i];
        float4 v = make_float4(acc[i][0] * inv, acc[i][1] * inv,
                               acc[i][2] * inv, acc[i][3] * inv);
        *(float4*)(og + (size_t)(ty * 4 + i) * 768 + tx * 4) = v;
    }
}

// ===========================================================================
// Launch
// ===========================================================================
extern "C" void kernel_launch(void* const* d_in, const int* in_sizes, int n_in,
                              void* d_out, int out_size)
{
    const float* query = (const float*)d_in[0];
    const float* attw  = (const float*)d_in[1];
    const float* Wq    = (const float*)d_in[2];
    const float* Wk    = (const float*)d_in[3];
    const float* Wv    = (const float*)d_in[4];
    const float* Wo    = (const float*)d_in[5];
    const float* bo    = (const float*)d_in[6];
    float* out = (float*)d_out;

    float *qkv = nullptr, *att = nullptr;
    __nv_bfloat16 *ahi = nullptr, *alo = nullptr, *whi = nullptr, *wlo = nullptr;
    cudaGetSymbolAddress((void**)&qkv, g_qkv);
    cudaGetSymbolAddress((void**)&att, g_att);
    cudaGetSymbolAddress((void**)&ahi, g_ahi);
    cudaGetSymbolAddress((void**)&alo, g_alo);
    cudaGetSymbolAddress((void**)&whi, g_whi);
    cudaGetSymbolAddress((void**)&wlo, g_wlo);

    const int attn_smem = 4 * 64 * 68 * (int)sizeof(float);
    cudaFuncSetAttribute(attn_fused, cudaFuncAttributeMaxDynamicSharedMemorySize, attn_smem);
    const int gemm_smem = 4 * 128 * AST * (int)sizeof(__nv_bfloat16);  // 73728
    cudaFuncSetAttribute(gemm_mma, cudaFuncAttributeMaxDynamicSharedMemorySize, gemm_smem);

    // 1) Split activations + weights into bf16 hi/lo
    split_f32<<<TOTE / 4 / 256, 256>>>((const float4*)query, (uint2*)ahi, (uint2*)alo, TOTE / 4);
    split_f32<<<WELE / 4 / 256, 256>>>((const float4*)Wq, (uint2*)(whi + 0 * WELE), (uint2*)(wlo + 0 * WELE), WELE / 4);
    split_f32<<<WELE / 4 / 256, 256>>>((const float4*)Wk, (uint2*)(whi + 1 * WELE), (uint2*)(wlo + 1 * WELE), WELE / 4);
    split_f32<<<WELE / 4 / 256, 256>>>((const float4*)Wv, (uint2*)(whi + 2 * WELE), (uint2*)(wlo + 2 * WELE), WELE / 4);
    split_f32<<<WELE / 4 / 256, 256>>>((const float4*)Wo, (uint2*)(whi + 3 * WELE), (uint2*)(wlo + 3 * WELE), WELE / 4);

    // 2) QKV projections on HMMA tensor path (z selects weight + output slab)
    gemm_mma<<<dim3(6, 32, 3), 256, gemm_smem>>>(ahi, alo, whi, wlo, nullptr, qkv);

    // 3) Fused biased attention (fp32)
    attn_fused<<<dim3(16, 12, 4), 256, attn_smem>>>(qkv, attw, att);

    // 4) Output projection on HMMA tensor path
    split_f32<<<TOTE / 4 / 256, 256>>>((const float4*)att, (uint2*)ahi, (uint2*)alo, TOTE / 4);
    gemm_mma<<<dim3(6, 32, 1), 256, gemm_smem>>>(ahi, alo, whi + 3 * WELE, wlo + 3 * WELE, bo, out);
}

// round 5
// speedup vs baseline: 2.6185x; 1.8137x over previous
#include <cuda_runtime.h>
#include <cuda_bf16.h>
#include <cuda_fp16.h>
#include <math.h>
#include <cstdint>

#define TOTE (4096 * 768)
#define WELE (768 * 768)
#define AST 72     // smem row stride in elements (144B: conflict-free ldmatrix)

// Scratch (allocation-free rule: __device__ globals)
__device__ __nv_bfloat16 g_ahi[TOTE];        // activation split (query, then att out)
__device__ __nv_bfloat16 g_alo[TOTE];
__device__ __nv_bfloat16 g_whi[4 * WELE];    // Wq|Wk|Wv|Wo hi
__device__ __nv_bfloat16 g_wlo[4 * WELE];
__device__ __nv_bfloat16 g_qkh[2 * TOTE];    // Q|K hi (from QKV gemm epilogue)
__device__ __nv_bfloat16 g_qkl[2 * TOTE];    // Q|K lo
__device__ __half        g_vf[TOTE];         // V fp16

// ===========================================================================
// Base-sm_103-safe helpers (no tcgen05: ptxas virtual target is compute_103)
// ===========================================================================
__device__ __forceinline__ uint32_t smem_u32(const void* p) {
    uint32_t a;
    asm("{ .reg .u64 t; cvta.to.shared.u64 t, %1; cvt.u32.u64 %0, t; }" : "=r"(a) : "l"(p));
    return a;
}
__device__ __forceinline__ void ldsm_x4(uint32_t* r, uint32_t addr) {
    asm volatile("ldmatrix.sync.aligned.m8n8.x4.shared.b16 {%0,%1,%2,%3}, [%4];"
                 : "=r"(r[0]), "=r"(r[1]), "=r"(r[2]), "=r"(r[3]) : "r"(addr));
}
__device__ __forceinline__ void ldsm_x4_t(uint32_t* r, uint32_t addr) {
    asm volatile("ldmatrix.sync.aligned.m8n8.x4.trans.shared.b16 {%0,%1,%2,%3}, [%4];"
                 : "=r"(r[0]), "=r"(r[1]), "=r"(r[2]), "=r"(r[3]) : "r"(addr));
}
__device__ __forceinline__ void mma_bf(float* d, const uint32_t* a, uint32_t b0, uint32_t b1) {
    asm volatile(
        "mma.sync.aligned.m16n8k16.row.col.f32.bf16.bf16.f32 "
        "{%0,%1,%2,%3}, {%4,%5,%6,%7}, {%8,%9}, {%0,%1,%2,%3};"
        : "+f"(d[0]), "+f"(d[1]), "+f"(d[2]), "+f"(d[3])
        : "r"(a[0]), "r"(a[1]), "r"(a[2]), "r"(a[3]), "r"(b0), "r"(b1));
}
__device__ __forceinline__ void mma_f16(float* d, const uint32_t* a, uint32_t b0, uint32_t b1) {
    asm volatile(
        "mma.sync.aligned.m16n8k16.row.col.f32.f16.f16.f32 "
        "{%0,%1,%2,%3}, {%4,%5,%6,%7}, {%8,%9}, {%0,%1,%2,%3};"
        : "+f"(d[0]), "+f"(d[1]), "+f"(d[2]), "+f"(d[3])
        : "r"(a[0]), "r"(a[1]), "r"(a[2]), "r"(a[3]), "r"(b0), "r"(b1));
}
__device__ __forceinline__ uint32_t pack_f16x2(float lo, float hi) {
    uint32_t d;
    asm("cvt.rn.f16x2.f32 %0, %1, %2;" : "=r"(d) : "f"(hi), "f"(lo));
    return d;
}
__device__ __forceinline__ void cpa16(uint32_t dst, const void* src) {
    asm volatile("cp.async.cg.shared.global [%0], [%1], 16;" :: "r"(dst), "l"(src) : "memory");
}

// ===========================================================================
// fp32 -> bf16 hi/lo split (query + weights only now)
// ===========================================================================
__global__ __launch_bounds__(256) void split_f32(
    const float4* __restrict__ x, uint2* __restrict__ hi, uint2* __restrict__ lo, int n4)
{
    int i = blockIdx.x * blockDim.x + threadIdx.x;
    if (i >= n4) return;
    float4 v = x[i];
    float vv[4] = {v.x, v.y, v.z, v.w};
    __nv_bfloat16 h[4], l[4];
#pragma unroll
    for (int j = 0; j < 4; j++) {
        h[j] = __float2bfloat16(vv[j]);
        l[j] = __float2bfloat16(vv[j] - __bfloat162float(h[j]));
    }
    hi[i] = *(uint2*)h;
    lo[i] = *(uint2*)l;
}

// ===========================================================================
// HMMA split-bf16 NT GEMM, cp.async double-buffered.
// Epilogue modes: Cf!=null -> fp32+bias; else z==2 -> fp16 (V); else bf16 hi/lo.
// ===========================================================================
__global__ __launch_bounds__(256) void gemm_mma(
    const __nv_bfloat16* __restrict__ Ahi, const __nv_bfloat16* __restrict__ Alo,
    const __nv_bfloat16* __restrict__ Whi, const __nv_bfloat16* __restrict__ Wlo,
    const float* __restrict__ bias, float* __restrict__ Cf,
    __nv_bfloat16* __restrict__ Chi, __nv_bfloat16* __restrict__ Clo,
    __half* __restrict__ Cf16, int wbase)
{
    extern __shared__ __align__(16) __nv_bfloat16 smb[];
    const int TILEB = 128 * AST * 2;   // bytes per array
    const uint32_t sb = smem_u32(smb);

    const int tid = threadIdx.x, wid = tid >> 5, lane = tid & 31;
    const int wm = (wid >> 1) * 32, wn = (wid & 1) * 64;
    const int m0 = blockIdx.y * 128, n0 = blockIdx.x * 128;
    const int z = blockIdx.z;

    const __nv_bfloat16* gAh = Ahi + (size_t)m0 * 768;
    const __nv_bfloat16* gAl = Alo + (size_t)m0 * 768;
    const __nv_bfloat16* gBh = Whi + (size_t)(wbase + z) * WELE + (size_t)n0 * 768;
    const __nv_bfloat16* gBl = Wlo + (size_t)(wbase + z) * WELE + (size_t)n0 * 768;

    float acc[2][8][4];
#pragma unroll
    for (int i = 0; i < 2; i++)
#pragma unroll
        for (int j = 0; j < 8; j++)
#pragma unroll
            for (int k = 0; k < 4; k++) acc[i][j][k] = 0.f;

#define GSTAGE(buf, k0)                                                        \
    {                                                                          \
        uint32_t base_ = sb + (buf) * (4 * TILEB);                             \
        _Pragma("unroll")                                                      \
        for (int it = 0; it < 4; it++) {                                       \
            int idx = it * 256 + tid;                                          \
            int row = idx >> 3, cc = idx & 7;                                  \
            uint32_t off = (uint32_t)(row * AST + cc * 8) * 2;                 \
            size_t go = (size_t)row * 768 + (k0) + cc * 8;                     \
            cpa16(base_ + off,             gAh + go);                          \
            cpa16(base_ + TILEB + off,     gAl + go);                          \
            cpa16(base_ + 2 * TILEB + off, gBh + go);                          \
            cpa16(base_ + 3 * TILEB + off, gBl + go);                          \
        }                                                                      \
        asm volatile("cp.async.commit_group;" ::: "memory");                   \
    }

    GSTAGE(0, 0);

    const int lrow = lane & 15, lcol8 = (lane >> 4) * 8;
    const uint32_t offA = (uint32_t)((wm + lrow) * AST + lcol8) * 2;
    const uint32_t offB = (uint32_t)((wn + lrow) * AST + lcol8) * 2;

    for (int c = 0; c < 12; c++) {
        if (c + 1 < 12) {
            GSTAGE((c + 1) & 1, (c + 1) * 64);
            asm volatile("cp.async.wait_group 1;" ::: "memory");
        } else {
            asm volatile("cp.async.wait_group 0;" ::: "memory");
        }
        __syncthreads();
        uint32_t base = sb + (c & 1) * (4 * TILEB);
        uint32_t aAh = base + offA, aAl = base + TILEB + offA;
        uint32_t aBh = base + 2 * TILEB + offB, aBl = base + 3 * TILEB + offB;
#pragma unroll
        for (int kk = 0; kk < 64; kk += 16) {
            const uint32_t koff = kk * 2;
            uint32_t ah[2][4], al[2][4], bh[4][4], bl[4][4];
#pragma unroll
            for (int mf = 0; mf < 2; mf++) {
                ldsm_x4(ah[mf], aAh + mf * 16 * AST * 2 + koff);
                ldsm_x4(al[mf], aAl + mf * 16 * AST * 2 + koff);
            }
#pragma unroll
            for (int nq = 0; nq < 4; nq++) {
                ldsm_x4(bh[nq], aBh + nq * 16 * AST * 2 + koff);
                ldsm_x4(bl[nq], aBl + nq * 16 * AST * 2 + koff);
            }
#pragma unroll
            for (int mf = 0; mf < 2; mf++) {
#pragma unroll
                for (int nq = 0; nq < 4; nq++) {
                    float* a0 = acc[mf][nq * 2 + 0];
                    float* a1 = acc[mf][nq * 2 + 1];
                    mma_bf(a0, ah[mf], bh[nq][0], bh[nq][2]);   // hi*hi
                    mma_bf(a1, ah[mf], bh[nq][1], bh[nq][3]);
                    mma_bf(a0, al[mf], bh[nq][0], bh[nq][2]);   // lo*hi
                    mma_bf(a1, al[mf], bh[nq][1], bh[nq][3]);
                    mma_bf(a0, ah[mf], bl[nq][0], bl[nq][2]);   // hi*lo
                    mma_bf(a1, ah[mf], bl[nq][1], bl[nq][3]);
                }
            }
        }
        __syncthreads();
    }

    // Epilogue (frag rows lane>>2 + {0,8}, cols (lane&3)*2 + {0,1})
#pragma unroll
    for (int mf = 0; mf < 2; mf++) {
#pragma unroll
        for (int nf = 0; nf < 8; nf++) {
            int row = m0 + wm + mf * 16 + (lane >> 2);
            int col = n0 + wn + nf * 8 + (lane & 3) * 2;
            float v0 = acc[mf][nf][0], v1 = acc[mf][nf][1];
            float v2 = acc[mf][nf][2], v3 = acc[mf][nf][3];
            if (Cf) {
                float b0 = bias[col], b1 = bias[col + 1];
                *(float2*)(Cf + (size_t)row * 768 + col) = make_float2(v0 + b0, v1 + b1);
                *(float2*)(Cf + (size_t)(row + 8) * 768 + col) = make_float2(v2 + b0, v3 + b1);
            } else if (z == 2) {
                __half2 h0 = __floats2half2_rn(v0, v1);
                __half2 h1 = __floats2half2_rn(v2, v3);
                *(uint32_t*)(Cf16 + (size_t)row * 768 + col) = *(uint32_t*)&h0;
                *(uint32_t*)(Cf16 + (size_t)(row + 8) * 768 + col) = *(uint32_t*)&h1;
            } else {
                __nv_bfloat16* ch = Chi + (size_t)z * TOTE;
                __nv_bfloat16* cl = Clo + (size_t)z * TOTE;
                __nv_bfloat16 h0 = __float2bfloat16(v0), h1 = __float2bfloat16(v1);
                __nv_bfloat16 h2 = __float2bfloat16(v2), h3 = __float2bfloat16(v3);
                __nv_bfloat162 ph0 = {h0, h1}, ph1 = {h2, h3};
                __nv_bfloat162 pl0 = {__float2bfloat16(v0 - __bfloat162float(h0)),
                                      __float2bfloat16(v1 - __bfloat162float(h1))};
                __nv_bfloat162 pl1 = {__float2bfloat16(v2 - __bfloat162float(h2)),
                                      __float2bfloat16(v3 - __bfloat162float(h3))};
                *(uint32_t*)(ch + (size_t)row * 768 + col) = *(uint32_t*)&ph0;
                *(uint32_t*)(ch + (size_t)(row + 8) * 768 + col) = *(uint32_t*)&ph1;
                *(uint32_t*)(cl + (size_t)row * 768 + col) = *(uint32_t*)&pl0;
                *(uint32_t*)(cl + (size_t)(row + 8) * 768 + col) = *(uint32_t*)&pl1;
            }
        }
    }
}

// ===========================================================================
// HMMA fused biased flash attention.
// softmax(W + log_softmax(s*QK^T)) == softmax(W + s*QK^T)  (LSE cancels)
// Block: 128 threads (4 warps x 16 queries = 64 q). Key tile = 128.
// QK: split-bf16 3-term. PV: fp16 single-term; P stays in registers
// (S-accum fragment layout == A fragment layout for the next mma).
// ===========================================================================
__global__ __launch_bounds__(128, 2) void attn_mma(
    const __nv_bfloat16* __restrict__ qkh, const __nv_bfloat16* __restrict__ qkl,
    const __half* __restrict__ vf, const float* __restrict__ W,
    __nv_bfloat16* __restrict__ ohi, __nv_bfloat16* __restrict__ olo)
{
    extern __shared__ __align__(16) char smn[];
    __nv_bfloat16* sKh = (__nv_bfloat16*)smn;            // [128][AST]
    __nv_bfloat16* sKl = sKh + 128 * AST;
    __half*        sV  = (__half*)(sKl + 128 * AST);     // [128][AST]

    const int tid = threadIdx.x, wp = tid >> 5, lane = tid & 31;
    const int n0 = blockIdx.x * 64, h = blockIdx.y, b = blockIdx.z;

    const __nv_bfloat16* qh = qkh + ((size_t)(b * 1024 + n0)) * 768 + h * 64;
    const __nv_bfloat16* ql = qkl + ((size_t)(b * 1024 + n0)) * 768 + h * 64;
    const __nv_bfloat16* kh = qkh + (size_t)TOTE + (size_t)b * 1024 * 768 + h * 64;
    const __nv_bfloat16* kl = qkl + (size_t)TOTE + (size_t)b * 1024 * 768 + h * 64;
    const __half* vg = vf + (size_t)b * 1024 * 768 + h * 64;
    const float* wg = W + ((size_t)(b * 12 + h) * 1024 + n0) * 1024;

    // --- Stage Q (64x64) hi/lo into sKh/sKl, pull A-frags into registers ---
#pragma unroll
    for (int it = 0; it < 4; it++) {
        int idx = it * 128 + tid;
        int row = idx >> 3, cc = idx & 7;
        *(uint4*)(sKh + row * AST + cc * 8) = *(const uint4*)(qh + (size_t)row * 768 + cc * 8);
        *(uint4*)(sKl + row * AST + cc * 8) = *(const uint4*)(ql + (size_t)row * 768 + cc * 8);
    }
    __syncthreads();
    uint32_t qfh[4][4], qfl[4][4];
    {
        uint32_t bh_ = smem_u32(sKh) + (uint32_t)((wp * 16 + (lane & 15)) * AST + (lane >> 4) * 8) * 2;
        uint32_t bl_ = smem_u32(sKl) + (uint32_t)((wp * 16 + (lane & 15)) * AST + (lane >> 4) * 8) * 2;
#pragma unroll
        for (int ks = 0; ks < 4; ks++) {
            ldsm_x4(qfh[ks], bh_ + ks * 32);
            ldsm_x4(qfl[ks], bl_ + ks * 32);
        }
    }
    __syncthreads();

    float oacc[8][4];
#pragma unroll
    for (int d = 0; d < 8; d++)
#pragma unroll
        for (int j = 0; j < 4; j++) oacc[d][j] = 0.f;
    float m0r = -INFINITY, m1r = -INFINITY, l0r = 0.f, l1r = 0.f;

    const uint32_t kbh = smem_u32(sKh) + (uint32_t)(((lane & 15) * AST) + (lane >> 4) * 8) * 2;
    const uint32_t kbl = smem_u32(sKl) + (uint32_t)(((lane & 15) * AST) + (lane >> 4) * 8) * 2;
    const uint32_t vbb = smem_u32(sV)  + (uint32_t)(((lane & 15) * AST) + (lane >> 4) * 8) * 2;
    const uint32_t skh0 = smem_u32(sKh), skl0 = smem_u32(sKl), sv0 = smem_u32(sV);

    for (int s0 = 0; s0 < 1024; s0 += 128) {
        __syncthreads();   // prior tile's ldsm reads done
#pragma unroll
        for (int it = 0; it < 8; it++) {
            int idx = it * 128 + tid;
            int row = idx >> 3, cc = idx & 7;
            uint32_t doff = (uint32_t)(row * AST + cc * 8) * 2;
            size_t go = (size_t)(s0 + row) * 768 + cc * 8;
            cpa16(skh0 + doff, kh + go);
            cpa16(skl0 + doff, kl + go);
            cpa16(sv0 + doff, vg + go);
        }
        asm volatile("cp.async.commit_group;" ::: "memory");
        asm volatile("cp.async.wait_group 0;" ::: "memory");
        __syncthreads();

        // ---- S = Q K^T (3-term split-bf16) ----
        float sc[16][4];
#pragma unroll
        for (int nf = 0; nf < 16; nf++)
#pragma unroll
            for (int j = 0; j < 4; j++) sc[nf][j] = 0.f;
#pragma unroll
        for (int nf2 = 0; nf2 < 8; nf2++) {
#pragma unroll
            for (int ks = 0; ks < 4; ks++) {
                uint32_t off = (uint32_t)(nf2 * 16 * AST + ks * 16) * 2;
                uint32_t fh[4], fl[4];
                ldsm_x4(fh, kbh + off);
                ldsm_x4(fl, kbl + off);
                mma_bf(sc[2 * nf2],     qfh[ks], fh[0], fh[2]);
                mma_bf(sc[2 * nf2 + 1], qfh[ks], fh[1], fh[3]);
                mma_bf(sc[2 * nf2],     qfl[ks], fh[0], fh[2]);
                mma_bf(sc[2 * nf2 + 1], qfl[ks], fh[1], fh[3]);
                mma_bf(sc[2 * nf2],     qfh[ks], fl[0], fl[2]);
                mma_bf(sc[2 * nf2 + 1], qfh[ks], fl[1], fl[3]);
            }
        }

        // ---- bias + online softmax (rows lane>>2 and lane>>2+8) ----
        const int c0 = (lane & 3) * 2;
        const float* wrow0 = wg + (size_t)(wp * 16 + (lane >> 2)) * 1024 + s0;
        const float* wrow1 = wrow0 + 8 * 1024;
        float nm0 = m0r, nm1 = m1r;
#pragma unroll
        for (int nf = 0; nf < 16; nf++) {
            float2 w0 = *(const float2*)(wrow0 + nf * 8 + c0);
            float2 w1 = *(const float2*)(wrow1 + nf * 8 + c0);
            sc[nf][0] = fmaf(sc[nf][0], 0.125f, w0.x);
            sc[nf][1] = fmaf(sc[nf][1], 0.125f, w0.y);
            sc[nf][2] = fmaf(sc[nf][2], 0.125f, w1.x);
            sc[nf][3] = fmaf(sc[nf][3], 0.125f, w1.y);
            nm0 = fmaxf(nm0, fmaxf(sc[nf][0], sc[nf][1]));
            nm1 = fmaxf(nm1, fmaxf(sc[nf][2], sc[nf][3]));
        }
        nm0 = fmaxf(nm0, __shfl_xor_sync(0xffffffffu, nm0, 1));
        nm0 = fmaxf(nm0, __shfl_xor_sync(0xffffffffu, nm0, 2));
        nm1 = fmaxf(nm1, __shfl_xor_sync(0xffffffffu, nm1, 1));
        nm1 = fmaxf(nm1, __shfl_xor_sync(0xffffffffu, nm1, 2));
        float corr0 = __expf(m0r - nm0), corr1 = __expf(m1r - nm1);
        m0r = nm0; m1r = nm1;
        float rs0 = 0.f, rs1 = 0.f;
#pragma unroll
        for (int nf = 0; nf < 16; nf++) {
            sc[nf][0] = __expf(sc[nf][0] - nm0);
            sc[nf][1] = __expf(sc[nf][1] - nm0);
            sc[nf][2] = __expf(sc[nf][2] - nm1);
            sc[nf][3] = __expf(sc[nf][3] - nm1);
            rs0 += sc[nf][0] + sc[nf][1];
            rs1 += sc[nf][2] + sc[nf][3];
        }
        l0r = l0r * corr0 + rs0;
        l1r = l1r * corr1 + rs1;
#pragma unroll
        for (int d = 0; d < 8; d++) {
            oacc[d][0] *= corr0; oacc[d][1] *= corr0;
            oacc[d][2] *= corr1; oacc[d][3] *= corr1;
        }

        // ---- out += P V (fp16, P from registers) ----
#pragma unroll
        for (int kc = 0; kc < 8; kc++) {
            uint32_t pa[4];
            pa[0] = pack_f16x2(sc[2 * kc][0], sc[2 * kc][1]);
            pa[1] = pack_f16x2(sc[2 * kc][2], sc[2 * kc][3]);
            pa[2] = pack_f16x2(sc[2 * kc + 1][0], sc[2 * kc + 1][1]);
            pa[3] = pack_f16x2(sc[2 * kc + 1][2], sc[2 * kc + 1][3]);
#pragma unroll
            for (int dp = 0; dp < 4; dp++) {
                uint32_t vf4[4];
                ldsm_x4_t(vf4, vbb + (uint32_t)(kc * 16 * AST + dp * 16) * 2);
                mma_f16(oacc[2 * dp],     pa, vf4[0], vf4[1]);
                mma_f16(oacc[2 * dp + 1], pa, vf4[2], vf4[3]);
            }
        }
    }

    // ---- normalize + write bf16 hi/lo (att layout [4096, 768]) ----
    l0r += __shfl_xor_sync(0xffffffffu, l0r, 1);
    l0r += __shfl_xor_sync(0xffffffffu, l0r, 2);
    l1r += __shfl_xor_sync(0xffffffffu, l1r, 1);
    l1r += __shfl_xor_sync(0xffffffffu, l1r, 2);
    float i0 = 1.f / l0r, i1 = 1.f / l1r;
    int row = b * 1024 + n0 + wp * 16 + (lane >> 2);
    int colb = h * 64 + (lane & 3) * 2;
#pragma unroll
    for (int d = 0; d < 8; d++) {
        float v0 = oacc[d][0] * i0, v1 = oacc[d][1] * i0;
        float v2 = oacc[d][2] * i1, v3 = oacc[d][3] * i1;
        __nv_bfloat16 h0 = __float2bfloat16(v0), h1 = __float2bfloat16(v1);
        __nv_bfloat16 h2 = __float2bfloat16(v2), h3 = __float2bfloat16(v3);
        __nv_bfloat162 ph0 = {h0, h1}, ph1 = {h2, h3};
        __nv_bfloat162 pl0 = {__float2bfloat16(v0 - __bfloat162float(h0)),
                              __float2bfloat16(v1 - __bfloat162float(h1))};
        __nv_bfloat162 pl1 = {__float2bfloat16(v2 - __bfloat162float(h2)),
                              __float2bfloat16(v3 - __bfloat162float(h3))};
        *(uint32_t*)(ohi + (size_t)row * 768 + colb + d * 8) = *(uint32_t*)&ph0;
        *(uint32_t*)(ohi + (size_t)(row + 8) * 768 + colb + d * 8) = *(uint32_t*)&ph1;
        *(uint32_t*)(olo + (size_t)row * 768 + colb + d * 8) = *(uint32_t*)&pl0;
        *(uint32_t*)(olo + (size_t)(row + 8) * 768 + colb + d * 8) = *(uint32_t*)&pl1;
    }
}

// ===========================================================================
// Launch
// ===========================================================================
extern "C" void kernel_launch(void* const* d_in, const int* in_sizes, int n_in,
                              void* d_out, int out_size)
{
    const float* query = (const float*)d_in[0];
    const float* attw  = (const float*)d_in[1];
    const float* Wq    = (const float*)d_in[2];
    const float* Wk    = (const float*)d_in[3];
    const float* Wv    = (const float*)d_in[4];
    const float* Wo    = (const float*)d_in[5];
    const float* bo    = (const float*)d_in[6];
    float* out = (float*)d_out;

    __nv_bfloat16 *ahi, *alo, *whi, *wlo, *qkh, *qkl;
    __half* vfp;
    cudaGetSymbolAddress((void**)&ahi, g_ahi);
    cudaGetSymbolAddress((void**)&alo, g_alo);
    cudaGetSymbolAddress((void**)&whi, g_whi);
    cudaGetSymbolAddress((void**)&wlo, g_wlo);
    cudaGetSymbolAddress((void**)&qkh, g_qkh);
    cudaGetSymbolAddress((void**)&qkl, g_qkl);
    cudaGetSymbolAddress((void**)&vfp, g_vf);

    const int gemm_smem = 2 * 4 * 128 * AST * 2;   // 147456
    cudaFuncSetAttribute(gemm_mma, cudaFuncAttributeMaxDynamicSharedMemorySize, gemm_smem);
    const int attn_smem = 3 * 128 * AST * 2;       // 55296
    cudaFuncSetAttribute(attn_mma, cudaFuncAttributeMaxDynamicSharedMemorySize, attn_smem);

    // 1) Split query + weights into bf16 hi/lo
    split_f32<<<TOTE / 4 / 256, 256>>>((const float4*)query, (uint2*)ahi, (uint2*)alo, TOTE / 4);
    split_f32<<<WELE / 4 / 256, 256>>>((const float4*)Wq, (uint2*)(whi + 0 * WELE), (uint2*)(wlo + 0 * WELE), WELE / 4);
    split_f32<<<WELE / 4 / 256, 256>>>((const float4*)Wk, (uint2*)(whi + 1 * WELE), (uint2*)(wlo + 1 * WELE), WELE / 4);
    split_f32<<<WELE / 4 / 256, 256>>>((const float4*)Wv, (uint2*)(whi + 2 * WELE), (uint2*)(wlo + 2 * WELE), WELE / 4);
    split_f32<<<WELE / 4 / 256, 256>>>((const float4*)Wo, (uint2*)(whi + 3 * WELE), (uint2*)(wlo + 3 * WELE), WELE / 4);

    // 2) QKV: z<2 -> Q/K bf16 hi/lo, z==2 -> V fp16 (no fp32 round-trip)
    gemm_mma<<<dim3(6, 32, 3), 256, gemm_smem>>>(ahi, alo, whi, wlo,
                                                 nullptr, nullptr, qkh, qkl, vfp, 0);

    // 3) Fused biased attention on HMMA; writes att hi/lo into ahi/alo
    attn_mma<<<dim3(16, 12, 4), 128, attn_smem>>>(qkh, qkl, vfp, attw, ahi, alo);

    // 4) Output projection (fp32 + bias)
    gemm_mma<<<dim3(6, 32, 1), 256, gemm_smem>>>(ahi, alo, whi, wlo,
                                                 bo, out, nullptr, nullptr, nullptr, 3);
}

// round 6
// speedup vs baseline: 2.6949x; 1.0292x over previous
#include <cuda_runtime.h>
#include <cuda_bf16.h>
#include <cuda_fp16.h>
#include <math.h>
#include <cstdint>

#define TOTE (4096 * 768)
#define WELE (768 * 768)
#define AST 72     // bf16 smem row stride (144B: conflict-free ldmatrix)
#define WST 68     // W fp32 smem row stride (272B = 17*16B: cp.async-alignable)

// Scratch (allocation-free rule: __device__ globals)
__device__ __nv_bfloat16 g_ahi[TOTE];        // activation split (query, then att out)
__device__ __nv_bfloat16 g_alo[TOTE];
__device__ __nv_bfloat16 g_whi[4 * WELE];    // Wq|Wk|Wv|Wo hi
__device__ __nv_bfloat16 g_wlo[4 * WELE];
__device__ __nv_bfloat16 g_qkh[2 * TOTE];    // Q|K hi (from QKV gemm epilogue)
__device__ __nv_bfloat16 g_qkl[2 * TOTE];    // Q|K lo
__device__ __half        g_vf[TOTE];         // V fp16

// ===========================================================================
// Base-sm_103-safe helpers (no tcgen05: ptxas virtual target is compute_103)
// ===========================================================================
__device__ __forceinline__ uint32_t smem_u32(const void* p) {
    uint32_t a;
    asm("{ .reg .u64 t; cvta.to.shared.u64 t, %1; cvt.u32.u64 %0, t; }" : "=r"(a) : "l"(p));
    return a;
}
__device__ __forceinline__ void ldsm_x4(uint32_t* r, uint32_t addr) {
    asm volatile("ldmatrix.sync.aligned.m8n8.x4.shared.b16 {%0,%1,%2,%3}, [%4];"
                 : "=r"(r[0]), "=r"(r[1]), "=r"(r[2]), "=r"(r[3]) : "r"(addr));
}
__device__ __forceinline__ void ldsm_x4_t(uint32_t* r, uint32_t addr) {
    asm volatile("ldmatrix.sync.aligned.m8n8.x4.trans.shared.b16 {%0,%1,%2,%3}, [%4];"
                 : "=r"(r[0]), "=r"(r[1]), "=r"(r[2]), "=r"(r[3]) : "r"(addr));
}
__device__ __forceinline__ void mma_bf(float* d, const uint32_t* a, uint32_t b0, uint32_t b1) {
    asm volatile(
        "mma.sync.aligned.m16n8k16.row.col.f32.bf16.bf16.f32 "
        "{%0,%1,%2,%3}, {%4,%5,%6,%7}, {%8,%9}, {%0,%1,%2,%3};"
        : "+f"(d[0]), "+f"(d[1]), "+f"(d[2]), "+f"(d[3])
        : "r"(a[0]), "r"(a[1]), "r"(a[2]), "r"(a[3]), "r"(b0), "r"(b1));
}
__device__ __forceinline__ void mma_f16(float* d, const uint32_t* a, uint32_t b0, uint32_t b1) {
    asm volatile(
        "mma.sync.aligned.m16n8k16.row.col.f32.f16.f16.f32 "
        "{%0,%1,%2,%3}, {%4,%5,%6,%7}, {%8,%9}, {%0,%1,%2,%3};"
        : "+f"(d[0]), "+f"(d[1]), "+f"(d[2]), "+f"(d[3])
        : "r"(a[0]), "r"(a[1]), "r"(a[2]), "r"(a[3]), "r"(b0), "r"(b1));
}
__device__ __forceinline__ uint32_t pack_f16x2(float lo, float hi) {
    uint32_t d;
    asm("cvt.rn.f16x2.f32 %0, %1, %2;" : "=r"(d) : "f"(hi), "f"(lo));
    return d;
}
__device__ __forceinline__ void cpa16(uint32_t dst, const void* src) {
    asm volatile("cp.async.cg.shared.global [%0], [%1], 16;" :: "r"(dst), "l"(src) : "memory");
}

// ===========================================================================
// fp32 -> bf16 hi/lo splits
// ===========================================================================
__global__ __launch_bounds__(256) void split_f32(
    const float4* __restrict__ x, uint2* __restrict__ hi, uint2* __restrict__ lo, int n4)
{
    int i = blockIdx.x * blockDim.x + threadIdx.x;
    if (i >= n4) return;
    float4 v = x[i];
    float vv[4] = {v.x, v.y, v.z, v.w};
    __nv_bfloat16 h[4], l[4];
#pragma unroll
    for (int j = 0; j < 4; j++) {
        h[j] = __float2bfloat16(vv[j]);
        l[j] = __float2bfloat16(vv[j] - __bfloat162float(h[j]));
    }
    hi[i] = *(uint2*)h;
    lo[i] = *(uint2*)l;
}

// Batched weight split: z selects among the four weight matrices.
__global__ __launch_bounds__(256) void split_w(
    const float4* __restrict__ w0, const float4* __restrict__ w1,
    const float4* __restrict__ w2, const float4* __restrict__ w3,
    uint2* __restrict__ hi, uint2* __restrict__ lo)
{
    const int z = blockIdx.y;
    const float4* src = (z == 0) ? w0 : (z == 1) ? w1 : (z == 2) ? w2 : w3;
    int i = blockIdx.x * blockDim.x + threadIdx.x;
    if (i >= WELE / 4) return;
    float4 v = src[i];
    float vv[4] = {v.x, v.y, v.z, v.w};
    __nv_bfloat16 h[4], l[4];
#pragma unroll
    for (int j = 0; j < 4; j++) {
        h[j] = __float2bfloat16(vv[j]);
        l[j] = __float2bfloat16(vv[j] - __bfloat162float(h[j]));
    }
    hi[(size_t)z * (WELE / 4) + i] = *(uint2*)h;
    lo[(size_t)z * (WELE / 4) + i] = *(uint2*)l;
}

// ===========================================================================
// HMMA split-bf16 NT GEMM, cp.async double-buffered (unchanged from R5).
// ===========================================================================
__global__ __launch_bounds__(256) void gemm_mma(
    const __nv_bfloat16* __restrict__ Ahi, const __nv_bfloat16* __restrict__ Alo,
    const __nv_bfloat16* __restrict__ Whi, const __nv_bfloat16* __restrict__ Wlo,
    const float* __restrict__ bias, float* __restrict__ Cf,
    __nv_bfloat16* __restrict__ Chi, __nv_bfloat16* __restrict__ Clo,
    __half* __restrict__ Cf16, int wbase)
{
    extern __shared__ __align__(16) __nv_bfloat16 smb[];
    const int TILEB = 128 * AST * 2;
    const uint32_t sb = smem_u32(smb);

    const int tid = threadIdx.x, wid = tid >> 5, lane = tid & 31;
    const int wm = (wid >> 1) * 32, wn = (wid & 1) * 64;
    const int m0 = blockIdx.y * 128, n0 = blockIdx.x * 128;
    const int z = blockIdx.z;

    const __nv_bfloat16* gAh = Ahi + (size_t)m0 * 768;
    const __nv_bfloat16* gAl = Alo + (size_t)m0 * 768;
    const __nv_bfloat16* gBh = Whi + (size_t)(wbase + z) * WELE + (size_t)n0 * 768;
    const __nv_bfloat16* gBl = Wlo + (size_t)(wbase + z) * WELE + (size_t)n0 * 768;

    float acc[2][8][4];
#pragma unroll
    for (int i = 0; i < 2; i++)
#pragma unroll
        for (int j = 0; j < 8; j++)
#pragma unroll
            for (int k = 0; k < 4; k++) acc[i][j][k] = 0.f;

#define GSTAGE(buf, k0)                                                        \
    {                                                                          \
        uint32_t base_ = sb + (buf) * (4 * TILEB);                             \
        _Pragma("unroll")                                                      \
        for (int it = 0; it < 4; it++) {                                       \
            int idx = it * 256 + tid;                                          \
            int row = idx >> 3, cc = idx & 7;                                  \
            uint32_t off = (uint32_t)(row * AST + cc * 8) * 2;                 \
            size_t go = (size_t)row * 768 + (k0) + cc * 8;                     \
            cpa16(base_ + off,             gAh + go);                          \
            cpa16(base_ + TILEB + off,     gAl + go);                          \
            cpa16(base_ + 2 * TILEB + off, gBh + go);                          \
            cpa16(base_ + 3 * TILEB + off, gBl + go);                          \
        }                                                                      \
        asm volatile("cp.async.commit_group;" ::: "memory");                   \
    }

    GSTAGE(0, 0);

    const int lrow = lane & 15, lcol8 = (lane >> 4) * 8;
    const uint32_t offA = (uint32_t)((wm + lrow) * AST + lcol8) * 2;
    const uint32_t offB = (uint32_t)((wn + lrow) * AST + lcol8) * 2;

    for (int c = 0; c < 12; c++) {
        if (c + 1 < 12) {
            GSTAGE((c + 1) & 1, (c + 1) * 64);
            asm volatile("cp.async.wait_group 1;" ::: "memory");
        } else {
            asm volatile("cp.async.wait_group 0;" ::: "memory");
        }
        __syncthreads();
        uint32_t base = sb + (c & 1) * (4 * TILEB);
        uint32_t aAh = base + offA, aAl = base + TILEB + offA;
        uint32_t aBh = base + 2 * TILEB + offB, aBl = base + 3 * TILEB + offB;
#pragma unroll
        for (int kk = 0; kk < 64; kk += 16) {
            const uint32_t koff = kk * 2;
            uint32_t ah[2][4], al[2][4], bh[4][4], bl[4][4];
#pragma unroll
            for (int mf = 0; mf < 2; mf++) {
                ldsm_x4(ah[mf], aAh + mf * 16 * AST * 2 + koff);
                ldsm_x4(al[mf], aAl + mf * 16 * AST * 2 + koff);
            }
#pragma unroll
            for (int nq = 0; nq < 4; nq++) {
                ldsm_x4(bh[nq], aBh + nq * 16 * AST * 2 + koff);
                ldsm_x4(bl[nq], aBl + nq * 16 * AST * 2 + koff);
            }
#pragma unroll
            for (int mf = 0; mf < 2; mf++) {
#pragma unroll
                for (int nq = 0; nq < 4; nq++) {
                    float* a0 = acc[mf][nq * 2 + 0];
                    float* a1 = acc[mf][nq * 2 + 1];
                    mma_bf(a0, ah[mf], bh[nq][0], bh[nq][2]);
                    mma_bf(a1, ah[mf], bh[nq][1], bh[nq][3]);
                    mma_bf(a0, al[mf], bh[nq][0], bh[nq][2]);
                    mma_bf(a1, al[mf], bh[nq][1], bh[nq][3]);
                    mma_bf(a0, ah[mf], bl[nq][0], bl[nq][2]);
                    mma_bf(a1, ah[mf], bl[nq][1], bl[nq][3]);
                }
            }
        }
        __syncthreads();
    }

#pragma unroll
    for (int mf = 0; mf < 2; mf++) {
#pragma unroll
        for (int nf = 0; nf < 8; nf++) {
            int row = m0 + wm + mf * 16 + (lane >> 2);
            int col = n0 + wn + nf * 8 + (lane & 3) * 2;
            float v0 = acc[mf][nf][0], v1 = acc[mf][nf][1];
            float v2 = acc[mf][nf][2], v3 = acc[mf][nf][3];
            if (Cf) {
                float b0 = bias[col], b1 = bias[col + 1];
                *(float2*)(Cf + (size_t)row * 768 + col) = make_float2(v0 + b0, v1 + b1);
                *(float2*)(Cf + (size_t)(row + 8) * 768 + col) = make_float2(v2 + b0, v3 + b1);
            } else if (z == 2) {
                __half2 h0 = __floats2half2_rn(v0, v1);
                __half2 h1 = __floats2half2_rn(v2, v3);
                *(uint32_t*)(Cf16 + (size_t)row * 768 + col) = *(uint32_t*)&h0;
                *(uint32_t*)(Cf16 + (size_t)(row + 8) * 768 + col) = *(uint32_t*)&h1;
            } else {
                __nv_bfloat16* ch = Chi + (size_t)z * TOTE;
                __nv_bfloat16* cl = Clo + (size_t)z * TOTE;
                __nv_bfloat16 h0 = __float2bfloat16(v0), h1 = __float2bfloat16(v1);
                __nv_bfloat16 h2 = __float2bfloat16(v2), h3 = __float2bfloat16(v3);
                __nv_bfloat162 ph0 = {h0, h1}, ph1 = {h2, h3};
                __nv_bfloat162 pl0 = {__float2bfloat16(v0 - __bfloat162float(h0)),
                                      __float2bfloat16(v1 - __bfloat162float(h1))};
                __nv_bfloat162 pl1 = {__float2bfloat16(v2 - __bfloat162float(h2)),
                                      __float2bfloat16(v3 - __bfloat162float(h3))};
                *(uint32_t*)(ch + (size_t)row * 768 + col) = *(uint32_t*)&ph0;
                *(uint32_t*)(ch + (size_t)(row + 8) * 768 + col) = *(uint32_t*)&ph1;
                *(uint32_t*)(cl + (size_t)row * 768 + col) = *(uint32_t*)&pl0;
                *(uint32_t*)(cl + (size_t)(row + 8) * 768 + col) = *(uint32_t*)&pl1;
            }
        }
    }
}

// ===========================================================================
// HMMA fused biased flash attention, v2: 2-stage cp.async pipeline covering
// K hi/lo + V + the attn_weight (W) tile itself. 256 thr / 8 warps, 128
// queries per block, key tile 64. QK split-bf16 3-term; PV fp16 register-P.
// ===========================================================================
#define KVB (64 * AST * 2)            // bytes per K/V array per stage (9216)
#define WB  (128 * WST * 4)           // W tile bytes per stage (34816)
#define STB (3 * KVB + WB)            // stage stride (62464)

__global__ __launch_bounds__(256, 1) void attn_mma(
    const __nv_bfloat16* __restrict__ qkh, const __nv_bfloat16* __restrict__ qkl,
    const __half* __restrict__ vf, const float* __restrict__ W,
    __nv_bfloat16* __restrict__ ohi, __nv_bfloat16* __restrict__ olo)
{
    extern __shared__ __align__(16) char smn[];
    const uint32_t sb = smem_u32(smn);

    const int tid = threadIdx.x, wp = tid >> 5, lane = tid & 31;
    const int n0 = blockIdx.x * 128, h = blockIdx.y, b = blockIdx.z;

    const __nv_bfloat16* qh = qkh + ((size_t)(b * 1024 + n0)) * 768 + h * 64;
    const __nv_bfloat16* ql = qkl + ((size_t)(b * 1024 + n0)) * 768 + h * 64;
    const __nv_bfloat16* kh = qkh + (size_t)TOTE + (size_t)b * 1024 * 768 + h * 64;
    const __nv_bfloat16* kl = qkl + (size_t)TOTE + (size_t)b * 1024 * 768 + h * 64;
    const __half* vg = vf + (size_t)b * 1024 * 768 + h * 64;
    const float* wg = W + ((size_t)(b * 12 + h) * 1024 + n0) * 1024;

    // --- Stage Q (128x64) hi/lo through stage-0 smem, pull frags to regs ---
    {
        __nv_bfloat16* tQh = (__nv_bfloat16*)smn;
        __nv_bfloat16* tQl = tQh + 128 * AST;
#pragma unroll
        for (int it = 0; it < 4; it++) {
            int idx = it * 256 + tid;
            int row = idx >> 3, cc = idx & 7;
            *(uint4*)(tQh + row * AST + cc * 8) = *(const uint4*)(qh + (size_t)row * 768 + cc * 8);
            *(uint4*)(tQl + row * AST + cc * 8) = *(const uint4*)(ql + (size_t)row * 768 + cc * 8);
        }
    }
    __syncthreads();
    uint32_t qfh[4][4], qfl[4][4];
    {
        uint32_t off = (uint32_t)((wp * 16 + (lane & 15)) * AST + (lane >> 4) * 8) * 2;
#pragma unroll
        for (int ks = 0; ks < 4; ks++) {
            ldsm_x4(qfh[ks], sb + off + ks * 32);
            ldsm_x4(qfl[ks], sb + 128 * AST * 2 + off + ks * 32);
        }
    }
    __syncthreads();

    float oacc[8][4];
#pragma unroll
    for (int d = 0; d < 8; d++)
#pragma unroll
        for (int j = 0; j < 4; j++) oacc[d][j] = 0.f;
    float m0r = -INFINITY, m1r = -INFINITY, l0r = 0.f, l1r = 0.f;

#define ASTAGE(buf, s0_)                                                       \
    {                                                                          \
        uint32_t base_ = sb + (buf) * STB;                                     \
        _Pragma("unroll")                                                      \
        for (int it = 0; it < 2; it++) {                                       \
            int idx = it * 256 + tid;                                          \
            int row = idx >> 3, cc = idx & 7;                                  \
            uint32_t doff = (uint32_t)(row * AST + cc * 8) * 2;                \
            size_t go = (size_t)((s0_) + row) * 768 + cc * 8;                  \
            cpa16(base_ + doff,           kh + go);                            \
            cpa16(base_ + KVB + doff,     kl + go);                            \
            cpa16(base_ + 2 * KVB + doff, vg + go);                            \
        }                                                                      \
        _Pragma("unroll")                                                      \
        for (int it = 0; it < 8; it++) {                                       \
            int idx = it * 256 + tid;                                          \
            int row = idx >> 4, cc = idx & 15;                                 \
            cpa16(base_ + 3 * KVB + (uint32_t)(row * WST + cc * 4) * 4,        \
                  wg + (size_t)row * 1024 + (s0_) + cc * 4);                   \
        }                                                                      \
        asm volatile("cp.async.commit_group;" ::: "memory");                   \
    }

    ASTAGE(0, 0);

    const uint32_t foff = (uint32_t)(((lane & 15) * AST) + (lane >> 4) * 8) * 2;
    const int c0 = (lane & 3) * 2;
    const uint32_t woff = (uint32_t)((wp * 16 + (lane >> 2)) * WST + c0) * 4;

    for (int t = 0; t < 16; t++) {
        if (t + 1 < 16) {
            ASTAGE((t + 1) & 1, (t + 1) * 64);
            asm volatile("cp.async.wait_group 1;" ::: "memory");
        } else {
            asm volatile("cp.async.wait_group 0;" ::: "memory");
        }
        __syncthreads();
        uint32_t base = sb + (t & 1) * STB;
        uint32_t kbh = base + foff, kbl = base + KVB + foff;
        uint32_t vbb = base + 2 * KVB + foff;
        uint32_t wb0 = base + 3 * KVB + woff;

        // ---- S = Q K^T (3-term split-bf16), 64 keys ----
        float sc[8][4];
#pragma unroll
        for (int nf = 0; nf < 8; nf++)
#pragma unroll
            for (int j = 0; j < 4; j++) sc[nf][j] = 0.f;
#pragma unroll
        for (int nf2 = 0; nf2 < 4; nf2++) {
#pragma unroll
            for (int ks = 0; ks < 4; ks++) {
                uint32_t off = (uint32_t)(nf2 * 16 * AST + ks * 16) * 2;
                uint32_t fh[4], fl[4];
                ldsm_x4(fh, kbh + off);
                ldsm_x4(fl, kbl + off);
                mma_bf(sc[2 * nf2],     qfh[ks], fh[0], fh[2]);
                mma_bf(sc[2 * nf2 + 1], qfh[ks], fh[1], fh[3]);
                mma_bf(sc[2 * nf2],     qfl[ks], fh[0], fh[2]);
                mma_bf(sc[2 * nf2 + 1], qfl[ks], fh[1], fh[3]);
                mma_bf(sc[2 * nf2],     qfh[ks], fl[0], fl[2]);
                mma_bf(sc[2 * nf2 + 1], qfh[ks], fl[1], fl[3]);
            }
        }

        // ---- bias (from smem) + online softmax ----
        float nm0 = m0r, nm1 = m1r;
#pragma unroll
        for (int nf = 0; nf < 8; nf++) {
            float2 w0, w1;
            asm volatile("ld.shared.v2.f32 {%0,%1}, [%2];"
                         : "=f"(w0.x), "=f"(w0.y) : "r"(wb0 + nf * 32));
            asm volatile("ld.shared.v2.f32 {%0,%1}, [%2];"
                         : "=f"(w1.x), "=f"(w1.y) : "r"(wb0 + 8 * WST * 4 + nf * 32));
            sc[nf][0] = fmaf(sc[nf][0], 0.125f, w0.x);
            sc[nf][1] = fmaf(sc[nf][1], 0.125f, w0.y);
            sc[nf][2] = fmaf(sc[nf][2], 0.125f, w1.x);
            sc[nf][3] = fmaf(sc[nf][3], 0.125f, w1.y);
            nm0 = fmaxf(nm0, fmaxf(sc[nf][0], sc[nf][1]));
            nm1 = fmaxf(nm1, fmaxf(sc[nf][2], sc[nf][3]));
        }
        nm0 = fmaxf(nm0, __shfl_xor_sync(0xffffffffu, nm0, 1));
        nm0 = fmaxf(nm0, __shfl_xor_sync(0xffffffffu, nm0, 2));
        nm1 = fmaxf(nm1, __shfl_xor_sync(0xffffffffu, nm1, 1));
        nm1 = fmaxf(nm1, __shfl_xor_sync(0xffffffffu, nm1, 2));
        float corr0 = __expf(m0r - nm0), corr1 = __expf(m1r - nm1);
        m0r = nm0; m1r = nm1;
        float rs0 = 0.f, rs1 = 0.f;
#pragma unroll
        for (int nf = 0; nf < 8; nf++) {
            sc[nf][0] = __expf(sc[nf][0] - nm0);
            sc[nf][1] = __expf(sc[nf][1] - nm0);
            sc[nf][2] = __expf(sc[nf][2] - nm1);
            sc[nf][3] = __expf(sc[nf][3] - nm1);
            rs0 += sc[nf][0] + sc[nf][1];
            rs1 += sc[nf][2] + sc[nf][3];
        }
        l0r = l0r * corr0 + rs0;
        l1r = l1r * corr1 + rs1;
#pragma unroll
        for (int d = 0; d < 8; d++) {
            oacc[d][0] *= corr0; oacc[d][1] *= corr0;
            oacc[d][2] *= corr1; oacc[d][3] *= corr1;
        }

        // ---- out += P V (fp16, P from registers) ----
#pragma unroll
        for (int kc = 0; kc < 4; kc++) {
            uint32_t pa[4];
            pa[0] = pack_f16x2(sc[2 * kc][0], sc[2 * kc][1]);
            pa[1] = pack_f16x2(sc[2 * kc][2], sc[2 * kc][3]);
            pa[2] = pack_f16x2(sc[2 * kc + 1][0], sc[2 * kc + 1][1]);
            pa[3] = pack_f16x2(sc[2 * kc + 1][2], sc[2 * kc + 1][3]);
#pragma unroll
            for (int dp = 0; dp < 4; dp++) {
                uint32_t vf4[4];
                ldsm_x4_t(vf4, vbb + (uint32_t)(kc * 16 * AST + dp * 16) * 2);
                mma_f16(oacc[2 * dp],     pa, vf4[0], vf4[1]);
                mma_f16(oacc[2 * dp + 1], pa, vf4[2], vf4[3]);
            }
        }
        __syncthreads();
    }

    // ---- normalize + write bf16 hi/lo (att layout [4096, 768]) ----
    l0r += __shfl_xor_sync(0xffffffffu, l0r, 1);
    l0r += __shfl_xor_sync(0xffffffffu, l0r, 2);
    l1r += __shfl_xor_sync(0xffffffffu, l1r, 1);
    l1r += __shfl_xor_sync(0xffffffffu, l1r, 2);
    float i0 = 1.f / l0r, i1 = 1.f / l1r;
    int row = b * 1024 + n0 + wp * 16 + (lane >> 2);
    int colb = h * 64 + c0;
#pragma unroll
    for (int d = 0; d < 8; d++) {
        float v0 = oacc[d][0] * i0, v1 = oacc[d][1] * i0;
        float v2 = oacc[d][2] * i1, v3 = oacc[d][3] * i1;
        __nv_bfloat16 h0 = __float2bfloat16(v0), h1 = __float2bfloat16(v1);
        __nv_bfloat16 h2 = __float2bfloat16(v2), h3 = __float2bfloat16(v3);
        __nv_bfloat162 ph0 = {h0, h1}, ph1 = {h2, h3};
        __nv_bfloat162 pl0 = {__float2bfloat16(v0 - __bfloat162float(h0)),
                              __float2bfloat16(v1 - __bfloat162float(h1))};
        __nv_bfloat162 pl1 = {__float2bfloat16(v2 - __bfloat162float(h2)),
                              __float2bfloat16(v3 - __bfloat162float(h3))};
        *(uint32_t*)(ohi + (size_t)row * 768 + colb + d * 8) = *(uint32_t*)&ph0;
        *(uint32_t*)(ohi + (size_t)(row + 8) * 768 + colb + d * 8) = *(uint32_t*)&ph1;
        *(uint32_t*)(olo + (size_t)row * 768 + colb + d * 8) = *(uint32_t*)&pl0;
        *(uint32_t*)(olo + (size_t)(row + 8) * 768 + colb + d * 8) = *(uint32_t*)&pl1;
    }
}

// ===========================================================================
// Launch
// ===========================================================================
extern "C" void kernel_launch(void* const* d_in, const int* in_sizes, int n_in,
                              void* d_out, int out_size)
{
    const float* query = (const float*)d_in[0];
    const float* attw  = (const float*)d_in[1];
    const float* Wq    = (const float*)d_in[2];
    const float* Wk    = (const float*)d_in[3];
    const float* Wv    = (const float*)d_in[4];
    const float* Wo    = (const float*)d_in[5];
    const float* bo    = (const float*)d_in[6];
    float* out = (float*)d_out;

    __nv_bfloat16 *ahi, *alo, *whi, *wlo, *qkh, *qkl;
    __half* vfp;
    cudaGetSymbolAddress((void**)&ahi, g_ahi);
    cudaGetSymbolAddress((void**)&alo, g_alo);
    cudaGetSymbolAddress((void**)&whi, g_whi);
    cudaGetSymbolAddress((void**)&wlo, g_wlo);
    cudaGetSymbolAddress((void**)&qkh, g_qkh);
    cudaGetSymbolAddress((void**)&qkl, g_qkl);
    cudaGetSymbolAddress((void**)&vfp, g_vf);

    const int gemm_smem = 2 * 4 * 128 * AST * 2;   // 147456
    cudaFuncSetAttribute(gemm_mma, cudaFuncAttributeMaxDynamicSharedMemorySize, gemm_smem);
    const int attn_smem = 2 * STB;                 // 124928
    cudaFuncSetAttribute(attn_mma, cudaFuncAttributeMaxDynamicSharedMemorySize, attn_smem);

    // 1) Split query + all four weights (weights batched in one launch)
    split_f32<<<TOTE / 4 / 256, 256>>>((const float4*)query, (uint2*)ahi, (uint2*)alo, TOTE / 4);
    split_w<<<dim3(WELE / 4 / 256, 4), 256>>>((const float4*)Wq, (const float4*)Wk,
                                              (const float4*)Wv, (const float4*)Wo,
                                              (uint2*)whi, (uint2*)wlo);

    // 2) QKV: z<2 -> Q/K bf16 hi/lo, z==2 -> V fp16
    gemm_mma<<<dim3(6, 32, 3), 256, gemm_smem>>>(ahi, alo, whi, wlo,
                                                 nullptr, nullptr, qkh, qkl, vfp, 0);

    // 3) Fused biased attention (pipelined K/V/W); att hi/lo -> ahi/alo
    attn_mma<<<dim3(8, 12, 4), 256, attn_smem>>>(qkh, qkl, vfp, attw, ahi, alo);

    // 4) Output projection (fp32 + bias)
    gemm_mma<<<dim3(6, 32, 1), 256, gemm_smem>>>(ahi, alo, whi, wlo,
                                                 bo, out, nullptr, nullptr, nullptr, 3);
}